// round 1
// baseline (speedup 1.0000x reference)
#include <cuda_runtime.h>
#include <math.h>

#define N   8192
#define NZ  256
#define NC  128
#define DT_ 0.1f

// Scratch (allocation-guard-safe __device__ globals)
__device__ float g_r[N];    // r = tanh(x+b)
__device__ float g_z[NZ];   // z = W_rz @ r
__device__ float g_rn[N];   // r_new

__inline__ __device__ float block_reduce(float v) {
    __shared__ float sm[8];
    const int lane = threadIdx.x & 31;
    const int wid  = threadIdx.x >> 5;
    #pragma unroll
    for (int o = 16; o; o >>= 1) v += __shfl_down_sync(0xffffffffu, v, o);
    if (lane == 0) sm[wid] = v;
    __syncthreads();
    if (wid == 0) {
        v = (lane < 8) ? sm[lane] : 0.f;
        #pragma unroll
        for (int o = 4; o; o >>= 1) v += __shfl_down_sync(0xffffffffu, v, o);
    }
    return v;  // valid in thread 0
}

// Kernel 1: r = tanh(x + b)
__global__ void k_r(const float* __restrict__ x, const float* __restrict__ b) {
    int i = blockIdx.x * blockDim.x + threadIdx.x;
    if (i < N) g_r[i] = tanhf(x[i] + b[i]);
}

// Kernel 2: z = W_rz @ r   (256 rows, one block per row)
__global__ void k_z(const float* __restrict__ W_rz) {
    const int row = blockIdx.x;
    const float4* __restrict__ w = (const float4*)(W_rz + (size_t)row * N);
    const float4* __restrict__ v = (const float4*)g_r;
    float acc = 0.f;
    #pragma unroll 4
    for (int k = threadIdx.x; k < N / 4; k += 256) {
        float4 a = w[k], r4 = v[k];
        acc += a.x * r4.x + a.y * r4.y + a.z * r4.z + a.w * r4.w;
    }
    acc = block_reduce(acc);
    if (threadIdx.x == 0) g_z[row] = acc;
}

// Kernel 3: big fused row update.
// acc = W_rr[row,:]·r + W_epsr[row,:]·eps + W_zr[row,:]·z + W_cr[row,:]·c
// x_new = x + DT*(acc - x); r_new = tanh(x_new + b)
__global__ void __launch_bounds__(256) k_big(
    const float* __restrict__ W_rr, const float* __restrict__ W_zr,
    const float* __restrict__ W_cr, const float* __restrict__ W_epsr,
    const float* __restrict__ x,    const float* __restrict__ eps,
    const float* __restrict__ c,    const float* __restrict__ b,
    float* __restrict__ out)
{
    const int row = blockIdx.x;
    const int t   = threadIdx.x;

    const float4* __restrict__ w = (const float4*)(W_rr + (size_t)row * N);
    const float4* __restrict__ v = (const float4*)g_r;
    float acc = 0.f;
    #pragma unroll 4
    for (int k = t; k < N / 4; k += 256) {
        float4 a = w[k], r4 = v[k];
        acc += a.x * r4.x + a.y * r4.y + a.z * r4.z + a.w * r4.w;
    }

    // Side dots split across disjoint thread ranges (640 elems total)
    if (t < 64) {                               // W_epsr row: 256 f = 64 float4
        float4 a = ((const float4*)(W_epsr + (size_t)row * NZ))[t];
        float4 e = ((const float4*)eps)[t];
        acc += a.x * e.x + a.y * e.y + a.z * e.z + a.w * e.w;
    } else if (t < 128) {                       // W_zr row: 256 f = 64 float4
        int k = t - 64;
        float4 a = ((const float4*)(W_zr + (size_t)row * NZ))[k];
        float4 zz = ((const float4*)g_z)[k];
        acc += a.x * zz.x + a.y * zz.y + a.z * zz.z + a.w * zz.w;
    } else if (t < 160) {                       // W_cr row: 128 f = 32 float4
        int k = t - 128;
        float4 a = ((const float4*)(W_cr + (size_t)row * NC))[k];
        float4 cc = ((const float4*)c)[k];
        acc += a.x * cc.x + a.y * cc.y + a.z * cc.z + a.w * cc.w;
    }

    acc = block_reduce(acc);
    if (t == 0) {
        float xv = x[row];
        float xn = xv + DT_ * (acc - xv);
        out[row] = xn;
        float rn = tanhf(xn + b[row]);
        out[N + row] = rn;
        g_rn[row] = rn;
    }
}

// Kernel 4: z_new = W_rz @ r_new (rows 0..255), c_new = W_rc @ r_new (rows 256..383),
// eps_new = z_new - z_tilde fused.
__global__ void k_tail(const float* __restrict__ W_rz, const float* __restrict__ W_rc,
                       const float* __restrict__ z_tilde, float* __restrict__ out)
{
    const int bidx = blockIdx.x;
    const float* __restrict__ Wrow = (bidx < NZ)
        ? (W_rz + (size_t)bidx * N)
        : (W_rc + (size_t)(bidx - NZ) * N);
    const float4* __restrict__ w = (const float4*)Wrow;
    const float4* __restrict__ v = (const float4*)g_rn;
    float acc = 0.f;
    #pragma unroll 4
    for (int k = threadIdx.x; k < N / 4; k += 256) {
        float4 a = w[k], r4 = v[k];
        acc += a.x * r4.x + a.y * r4.y + a.z * r4.z + a.w * r4.w;
    }
    acc = block_reduce(acc);
    if (threadIdx.x == 0) {
        if (bidx < NZ) {
            out[2 * N + bidx] = acc;                              // z_new
            out[2 * N + NZ + NC + bidx] = acc - z_tilde[bidx];    // eps_new
        } else {
            out[2 * N + NZ + (bidx - NZ)] = acc;                  // c_new
        }
    }
}

extern "C" void kernel_launch(void* const* d_in, const int* in_sizes, int n_in,
                              void* d_out, int out_size) {
    // metadata order: x, eps, c, z_tilde, W_rr, W_zr, W_cr, W_epsr, W_rz, W_rc, b
    const float* x       = (const float*)d_in[0];
    const float* eps     = (const float*)d_in[1];
    const float* c       = (const float*)d_in[2];
    const float* z_tilde = (const float*)d_in[3];
    const float* W_rr    = (const float*)d_in[4];
    const float* W_zr    = (const float*)d_in[5];
    const float* W_cr    = (const float*)d_in[6];
    const float* W_epsr  = (const float*)d_in[7];
    const float* W_rz    = (const float*)d_in[8];
    const float* W_rc    = (const float*)d_in[9];
    const float* b       = (const float*)d_in[10];
    float* out = (float*)d_out;

    k_r   <<<N / 256, 256>>>(x, b);
    k_z   <<<NZ, 256>>>(W_rz);
    k_big <<<N, 256>>>(W_rr, W_zr, W_cr, W_epsr, x, eps, c, b, out);
    k_tail<<<NZ + NC, 256>>>(W_rz, W_rc, z_tilde, out);
}